// round 9
// baseline (speedup 1.0000x reference)
#include <cuda_runtime.h>
#include <math.h>

#define NH      8
#define LSEQ    512
#define DRES    384
#define DPAIR   128
#define DS      16
#define TJ      64
#define NROW    1024
#define NFEAT   1280
#define NSPLIT  4
#define KSPLIT  (NFEAT/NSPLIT)

#define SCALE_SCALAR 0.25f
#define SCALE_POINT  0.2357022603955158f   /* 18^-0.5 */
#define SCALE_TOTAL  0.5773502691896258f   /* 3^-0.5  */

typedef unsigned long long ull;

__device__ __forceinline__ ull pk2(float x, float y) {
    ull r; asm("mov.b64 %0,{%1,%2};" : "=l"(r) : "f"(x), "f"(y)); return r;
}
__device__ __forceinline__ ull ffma2(ull a, ull b, ull c) {
    ull d; asm("fma.rn.f32x2 %0,%1,%2,%3;" : "=l"(d) : "l"(a), "l"(b), "l"(c)); return d;
}
__device__ __forceinline__ float2 up2(ull v) {
    float2 r; asm("mov.b64 {%0,%1},%2;" : "=f"(r.x), "=f"(r.y) : "l"(v)); return r;
}
__device__ __forceinline__ void cp_async16(unsigned smem_addr, const void* gptr) {
    asm volatile("cp.async.cg.shared.global [%0], [%1], 16;"
                 :: "r"(smem_addr), "l"(gptr));
}

// ---------------- scratch (device globals; no allocation) ----------------
__device__ float g_qs[2*NH*LSEQ*DS];
__device__ float g_ks[2*NH*LSEQ*DS];
__device__ float g_vsT[2*NH*DS*LSEQ];     // [b][n][d][l]
__device__ float g_qp[2*NH*LSEQ*12];
__device__ float g_kp[2*NH*LSEQ*12];
__device__ float g_vpT[2*NH*12*LSEQ];     // [b][n][pc][l]
__device__ float g_praw[NROW*288];
__device__ float g_feat[(size_t)NROW*NFEAT];
__device__ float g_opart[(size_t)NSPLIT*NROW*DRES];

// ---------------- kernel 1: projection GEMM ------------------------------
__global__ void __launch_bounds__(64) proj_gemm(
    const float* __restrict__ X,
    const float* __restrict__ Wqs, const float* __restrict__ Wks,
    const float* __restrict__ Wvs, const float* __restrict__ Wqp,
    const float* __restrict__ Wkp, const float* __restrict__ Wvp)
{
    __shared__ float As[2][16*36];
    __shared__ float Bs[2][16*32];
    const int tid = threadIdx.x;
    const int tx = tid & 7, ty = tid >> 3;
    const int row0 = blockIdx.y * 32;
    const int col0 = blockIdx.x * 32;

    const float* Wseg; int segw, cl0;
    if (col0 < 384) {
        int sg = col0 >> 7;
        Wseg = (sg==0) ? Wqs : ((sg==1) ? Wks : Wvs);
        segw = 128; cl0 = col0 & 127;
    } else {
        int c2 = col0 - 384; int sg = c2 / 96;
        Wseg = (sg==0) ? Wqp : ((sg==1) ? Wkp : Wvp);
        segw = 96; cl0 = c2 - sg*96;
    }

    const int a_m0 = tid >> 2, a_k4 = tid & 3;
    const int b_k0 = tid >> 3, b_n4 = tid & 7;

    float acc[4][4];
    #pragma unroll
    for (int i=0;i<4;i++)
        #pragma unroll
        for (int j=0;j<4;j++) acc[i][j]=0.f;

    {
        #pragma unroll
        for (int s=0;s<2;s++) {
            int m = a_m0 + s*16;
            float4 v = *(const float4*)&X[(size_t)(row0+m)*DRES + a_k4*4];
            #pragma unroll
            for (int u=0;u<4;u++) As[0][(a_k4*4+u)*36 + m] = ((const float*)&v)[u];
            int k = b_k0 + s*8;
            *(float4*)&Bs[0][k*32 + b_n4*4] =
                *(const float4*)&Wseg[(size_t)k*segw + cl0 + b_n4*4];
        }
    }
    __syncthreads();

    const int KB = DRES/16;
    for (int kb = 0; kb < KB; kb++) {
        int cur = kb & 1;
        float4 va[2], vb[2];
        bool has = (kb+1 < KB);
        if (has) {
            int k0 = (kb+1)*16;
            #pragma unroll
            for (int s=0;s<2;s++) {
                int m = a_m0 + s*16;
                va[s] = *(const float4*)&X[(size_t)(row0+m)*DRES + k0 + a_k4*4];
                int k = b_k0 + s*8;
                vb[s] = *(const float4*)&Wseg[(size_t)(k0+k)*segw + cl0 + b_n4*4];
            }
        }
        #pragma unroll
        for (int kk = 0; kk < 16; kk++) {
            float4 a = *(const float4*)&As[cur][kk*36 + ty*4];
            float4 b = *(const float4*)&Bs[cur][kk*32 + tx*4];
            const float* ap = (const float*)&a;
            const float* bp = (const float*)&b;
            #pragma unroll
            for (int i=0;i<4;i++)
                #pragma unroll
                for (int j=0;j<4;j++) acc[i][j] += ap[i]*bp[j];
        }
        if (has) {
            int nxt = cur ^ 1;
            #pragma unroll
            for (int s=0;s<2;s++) {
                int m = a_m0 + s*16;
                #pragma unroll
                for (int u=0;u<4;u++) As[nxt][(a_k4*4+u)*36 + m] = ((const float*)&va[s])[u];
                int k = b_k0 + s*8;
                *(float4*)&Bs[nxt][k*32 + b_n4*4] = vb[s];
            }
        }
        __syncthreads();
    }

    #pragma unroll
    for (int i=0;i<4;i++) {
        int row = row0 + ty*4 + i;
        int b = row >> 9, l = row & 511;
        #pragma unroll
        for (int j=0;j<4;j++) {
            int col = col0 + tx*4 + j;
            float v = acc[i][j];
            if (col < 384) {
                int sg = col >> 7;
                int n = (col & 127) >> 4, d = col & 15;
                if (sg == 2)
                    g_vsT[(((b*NH)+n)*DS + d)*LSEQ + l] = v;
                else
                    ((sg==0) ? g_qs : g_ks)[(((b*NH)+n)*LSEQ + l)*DS + d] = v;
            } else {
                g_praw[row*288 + (col-384)] = v;
            }
        }
    }
}

// ---------------- kernel 2: euclid transform of projected points ---------
__global__ void point_transform(const float* __restrict__ R, const float* __restrict__ T)
{
    int row = blockIdx.x;
    int b = row >> 9, l = row & 511;
    int t = threadIdx.x;
    if (t >= 96) return;
    int tensor = t / 32, idx = t % 32;
    int n = idx >> 2, p = idx & 3;
    const float* xr = &g_praw[row*288 + tensor*96 + n*12 + p*3];
    const float* rr = &R[row*9];
    const float* tt = &T[row*3];
    float x0 = xr[0], x1 = xr[1], x2 = xr[2];
    float o[3];
    #pragma unroll
    for (int c = 0; c < 3; c++)
        o[c] = x0*rr[0*3+c] + x1*rr[1*3+c] + x2*rr[2*3+c] + tt[c];
    if (tensor == 2) {
        #pragma unroll
        for (int c = 0; c < 3; c++)
            g_vpT[(((b*NH)+n)*12 + p*3 + c)*LSEQ + l] = o[c];
    } else {
        float* dst = ((tensor==0) ? g_qp : g_kp) + (((b*NH)+n)*LSEQ + l)*12 + p*3;
        #pragma unroll
        for (int c = 0; c < 3; c++) dst[c] = o[c];
    }
}

// ---------------- kernel 3: fused IPA attention ---------------------------
// e tile stored XOR-swizzled: physical word = j*128 + (d ^ (4*(j&7)))
#define OFF_E0     0
#define OFF_E1     8192
#define OFF_WPBT   16384          /* wpbT[n][d], 8*128 */
#define OFF_LOGIT  17408          /* 8*66 */
#define OFF_PROB   17936          /* prob_s[n][j], pitch 68 */
#define OFF_PROBT  18480          /* probT[j][n], pitch 12 */
#define OFF_PART   19248          /* 256*9 */
#define OFF_QS     21552
#define OFF_QP     21680
#define OFF_GAMMA  21776
#define OFF_ALPHA  21784
#define OFF_DENOM  21792
#define OFF_OS     21800
#define OFF_OP     21928
#define SMEM_FLOATS 22024

__global__ void __launch_bounds__(256) ipa_attn(
    const float* __restrict__ E, const float* __restrict__ R,
    const float* __restrict__ T, const float* __restrict__ Wpb,
    const float* __restrict__ gamma)
{
    extern __shared__ float sm[];
    float* wpbT_s  = sm + OFF_WPBT;
    float* logit_s = sm + OFF_LOGIT;
    float* prob_s  = sm + OFF_PROB;
    float* probT_s = sm + OFF_PROBT;
    float* part_s  = sm + OFF_PART;
    float* qs_s    = sm + OFF_QS;
    float* qp_s    = sm + OFF_QP;
    float* gamma_s = sm + OFF_GAMMA;
    float* alpha_s = sm + OFF_ALPHA;
    float* denom_s = sm + OFF_DENOM;
    float* os_s    = sm + OFF_OS;
    float* op_s    = sm + OFF_OP;

    int row = blockIdx.x;
    int b = row >> 9, i = row & 511;
    int tid = threadIdx.x;
    int warp = tid >> 5, lane = tid & 31;

    unsigned sbase = (unsigned)__cvta_generic_to_shared(sm);
    const float* Ebi = E + (size_t)row * LSEQ * DPAIR;

    // prologue: tile 0 -> buffer 0 (swizzled)
    {
        const float4* esrc = (const float4*)Ebi;
        #pragma unroll
        for (int it = 0; it < 8; it++) {
            int g = it*256 + tid;
            int j = g >> 5, d = ((g & 31) * 4) ^ (4*(j & 7));
            cp_async16(sbase + (unsigned)((OFF_E0 + j*128 + d) * 4), esrc + g);
        }
        asm volatile("cp.async.commit_group;");
    }

    for (int k = tid; k < NH*DPAIR; k += 256) {
        int n = k >> 7, d = k & 127;
        wpbT_s[k] = Wpb[d*NH + n];
    }
    if (tid < 128) { int n = tid >> 4, d = tid & 15;
        qs_s[tid] = g_qs[((b*NH+n)*LSEQ + i)*DS + d]; }
    if (tid < 96)  { int n = tid/12, pc = tid - n*12;
        qp_s[tid] = g_qp[((b*NH+n)*LSEQ + i)*12 + pc]; }
    if (tid < 8) gamma_s[tid] = gamma[tid];

    float m_run = -1e30f, denom = 0.f, acc_sp = 0.f;
    float acc_e[NH][4];
    #pragma unroll
    for (int n=0;n<NH;n++)
        #pragma unroll
        for (int c=0;c<4;c++) acc_e[n][c] = 0.f;

    for (int jt = 0; jt < LSEQ/TJ; jt++) {
        float* e_s = sm + ((jt & 1) ? OFF_E1 : OFF_E0);

        if (jt + 1 < LSEQ/TJ) {
            const float4* nsrc = (const float4*)(Ebi + (size_t)(jt+1)*TJ*DPAIR);
            unsigned bofs = (jt & 1) ? OFF_E0 : OFF_E1;
            #pragma unroll
            for (int it = 0; it < 8; it++) {
                int g = it*256 + tid;
                int j = g >> 5, d = ((g & 31) * 4) ^ (4*(j & 7));
                cp_async16(sbase + (unsigned)((bofs + j*128 + d) * 4), nsrc + g);
            }
            asm volatile("cp.async.commit_group;");
            asm volatile("cp.async.wait_group 1;");
        } else {
            asm volatile("cp.async.wait_group 0;");
        }
        __syncthreads();

        int j0 = jt * TJ;

        // --- bias partials: thread (j, quad), e in regs, Wpb float4 bcast --
        {
            int j = tid & 63, quad = tid >> 6;
            int sw = 4*(j & 7);
            const float* eb = e_s + j*128;
            float4 e4[8];
            #pragma unroll
            for (int d4 = 0; d4 < 8; d4++)
                e4[d4] = *(const float4*)(eb + ((quad*32 + d4*4) ^ sw));
            float* po = part_s + (quad*64 + j)*9;
            #pragma unroll
            for (int n = 0; n < NH; n++) {
                const float4* wt = (const float4*)(wpbT_s + n*128 + quad*32);
                float s0=0.f, s1=0.f, s2=0.f, s3=0.f;
                #pragma unroll
                for (int d4 = 0; d4 < 8; d4++) {
                    float4 w = wt[d4];
                    s0 += e4[d4].x*w.x; s1 += e4[d4].y*w.y;
                    s2 += e4[d4].z*w.z; s3 += e4[d4].w*w.w;
                }
                po[n] = (s0+s1)+(s2+s3);
            }
        }
        __syncthreads();

        // --- full logits (2 heads per thread) ---
        {
            int j = tid & 63, nb = tid >> 6;
            #pragma unroll
            for (int h = 0; h < 2; h++) {
                int n = nb + h*4;
                float bias = part_s[(0*64+j)*9+n] + part_s[(1*64+j)*9+n]
                           + part_s[(2*64+j)*9+n] + part_s[(3*64+j)*9+n];
                const float4* kr = (const float4*)(g_ks + ((b*NH+n)*LSEQ + j0 + j)*DS);
                float dot = 0.f;
                #pragma unroll
                for (int q4 = 0; q4 < 4; q4++) {
                    float4 kv = kr[q4];
                    const float* qq = qs_s + n*DS + q4*4;
                    dot += qq[0]*kv.x + qq[1]*kv.y + qq[2]*kv.z + qq[3]*kv.w;
                }
                const float4* kp = (const float4*)(g_kp + ((b*NH+n)*LSEQ + j0 + j)*12);
                float sq = 0.f;
                #pragma unroll
                for (int q4 = 0; q4 < 3; q4++) {
                    float4 kv = kp[q4];
                    const float* qq = qp_s + n*12 + q4*4;
                    float d0 = qq[0]-kv.x, d1 = qq[1]-kv.y, d2 = qq[2]-kv.z, d3 = qq[3]-kv.w;
                    sq += d0*d0 + d1*d1 + d2*d2 + d3*d3;
                }
                logit_s[n*66 + j] = SCALE_TOTAL*(SCALE_SCALAR*dot + bias
                                    - 0.5f*SCALE_POINT*gamma_s[n]*sq);
            }
        }
        __syncthreads();

        // --- per-head online softmax + out_s / out_p (warp = head) ---
        {
            int n = warp;
            float l0 = logit_s[n*66 + lane], l1 = logit_s[n*66 + lane + 32];
            float mt = fmaxf(l0, l1);
            #pragma unroll
            for (int o = 16; o > 0; o >>= 1)
                mt = fmaxf(mt, __shfl_xor_sync(0xffffffffu, mt, o));
            float m_new = fmaxf(m_run, mt);
            float alpha = __expf(m_run - m_new);
            float p0 = __expf(l0 - m_new), p1 = __expf(l1 - m_new);
            prob_s[n*68 + lane]      = p0;
            prob_s[n*68 + lane + 32] = p1;
            probT_s[lane*12 + n]        = p0;
            probT_s[(lane+32)*12 + n]   = p1;
            float s = p0 + p1;
            #pragma unroll
            for (int o = 16; o > 0; o >>= 1)
                s += __shfl_xor_sync(0xffffffffu, s, o);
            denom = denom*alpha + s;
            m_run = m_new;
            if (lane == 0) alpha_s[n] = alpha;
            __syncwarp();
            acc_sp *= alpha;
            if (lane < 28) {
                const float* vb = (lane < 16)
                    ? g_vsT + ((size_t)(b*NH+n)*DS + lane)*LSEQ + j0
                    : g_vpT + ((size_t)(b*NH+n)*12 + (lane-16))*LSEQ + j0;
                const float* pr0 = prob_s + n*68;
                float a = 0.f;
                #pragma unroll
                for (int j4 = 0; j4 < 16; j4++) {
                    float4 vv = *(const float4*)&vb[j4*4];
                    float4 pp = *(const float4*)&pr0[j4*4];
                    a += pp.x*vv.x + pp.y*vv.y + pp.z*vv.z + pp.w*vv.w;
                }
                acc_sp += a;
            }
        }
        __syncthreads();

        // --- out_pair accumulate: warp owns j-slice, lane owns 4 dims -----
        {
            #pragma unroll
            for (int n=0;n<NH;n++) {
                float a = alpha_s[n];
                #pragma unroll
                for (int c=0;c<4;c++) acc_e[n][c] *= a;
            }
            int jb = warp*8;
            #pragma unroll
            for (int jj = 0; jj < 8; jj++) {
                int j = jb + jj;
                float4 pA = *(const float4*)&probT_s[j*12];
                float4 pB = *(const float4*)&probT_s[j*12 + 4];
                float4 ev = *(const float4*)(e_s + j*128 + ((lane*4) ^ (4*(j&7))));
                float pn[8] = {pA.x,pA.y,pA.z,pA.w,pB.x,pB.y,pB.z,pB.w};
                #pragma unroll
                for (int n=0;n<NH;n++) {
                    acc_e[n][0] += pn[n]*ev.x; acc_e[n][1] += pn[n]*ev.y;
                    acc_e[n][2] += pn[n]*ev.z; acc_e[n][3] += pn[n]*ev.w;
                }
            }
        }
        __syncthreads();
    }

    // ------------- finalize -------------
    float inv_d = 1.f / denom;
    if (lane == 0) denom_s[warp] = denom;
    if (lane < 16)      os_s[warp*16 + lane]        = acc_sp * inv_d;
    else if (lane < 28) op_s[warp*12 + (lane-16)]   = acc_sp * inv_d;
    __syncthreads();

    // cross-warp reduce of out_pair partials via e buffer 0 (8192 floats)
    float* red = sm + OFF_E0;
    #pragma unroll
    for (int n=0;n<NH;n++)
        *(float4*)(red + (warp*NH + n)*128 + lane*4) =
            make_float4(acc_e[n][0], acc_e[n][1], acc_e[n][2], acc_e[n][3]);
    __syncthreads();

    float* feat = g_feat + (size_t)row * NFEAT;
    #pragma unroll
    for (int k = 0; k < 4; k++) {
        int o = tid + k*256;
        int n = o >> 7, d = o & 127;
        float s = 0.f;
        #pragma unroll
        for (int w = 0; w < 8; w++) s += red[(w*NH+n)*128 + d];
        feat[128 + n*128 + d] = s / denom_s[n];
    }
    if (tid < 128) feat[tid] = os_s[tid];
    if (tid < 32) {
        int n = tid >> 2, p = tid & 3;
        const float* rr = R + row*9;
        const float* tt = T + row*3;
        float o0 = op_s[n*12+p*3+0] - tt[0];
        float o1 = op_s[n*12+p*3+1] - tt[1];
        float o2 = op_s[n*12+p*3+2] - tt[2];
        float nsq = 0.f;
        #pragma unroll
        for (int c = 0; c < 3; c++) {
            float lc = o0*rr[c*3+0] + o1*rr[c*3+1] + o2*rr[c*3+2];
            feat[1152 + n*12 + p*3 + c] = lc;
            nsq += lc*lc;
        }
        feat[1248 + n*4 + p] = sqrtf(nsq);
    }
}

// ------------- kernel 4: output GEMM, 4-way split-K partials --------------
__global__ void __launch_bounds__(64) out_gemm_sk(const float* __restrict__ Wout)
{
    __shared__ float As[2][16*36];
    __shared__ float Bs[2][16*32];
    const int tid = threadIdx.x;
    const int tx = tid & 7, ty = tid >> 3;
    const int row0 = blockIdx.y * 32;
    const int col0 = blockIdx.x * 32;
    const int kbase = blockIdx.z * KSPLIT;

    const int a_m0 = tid >> 2, a_k4 = tid & 3;
    const int b_k0 = tid >> 3, b_n4 = tid & 7;

    ull acc2[4][2];
    #pragma unroll
    for (int i=0;i<4;i++) { acc2[i][0]=0ull; acc2[i][1]=0ull; }

    {
        #pragma unroll
        for (int s=0;s<2;s++) {
            int m = a_m0 + s*16;
            float4 v = *(const float4*)&g_feat[(size_t)(row0+m)*NFEAT + kbase + a_k4*4];
            #pragma unroll
            for (int u=0;u<4;u++) As[0][(a_k4*4+u)*36 + m] = ((const float*)&v)[u];
            int k = b_k0 + s*8;
            *(float4*)&Bs[0][k*32 + b_n4*4] =
                *(const float4*)&Wout[(size_t)(kbase+k)*DRES + col0 + b_n4*4];
        }
    }
    __syncthreads();

    const int KB = KSPLIT/16;
    for (int kb = 0; kb < KB; kb++) {
        int cur = kb & 1;
        float4 va[2], vb[2];
        bool has = (kb+1 < KB);
        if (has) {
            int k0 = kbase + (kb+1)*16;
            #pragma unroll
            for (int s=0;s<2;s++) {
                int m = a_m0 + s*16;
                va[s] = *(const float4*)&g_feat[(size_t)(row0+m)*NFEAT + k0 + a_k4*4];
                int k = b_k0 + s*8;
                vb[s] = *(const float4*)&Wout[(size_t)(k0+k)*DRES + col0 + b_n4*4];
            }
        }
        #pragma unroll
        for (int kk = 0; kk < 16; kk++) {
            float4 a = *(const float4*)&As[cur][kk*36 + ty*4];
            float4 b = *(const float4*)&Bs[cur][kk*32 + tx*4];
            ull b01 = pk2(b.x, b.y), b23 = pk2(b.z, b.w);
            const float* ap = (const float*)&a;
            #pragma unroll
            for (int i=0;i<4;i++) {
                ull aa = pk2(ap[i], ap[i]);
                acc2[i][0] = ffma2(aa, b01, acc2[i][0]);
                acc2[i][1] = ffma2(aa, b23, acc2[i][1]);
            }
        }
        if (has) {
            int nxt = cur ^ 1;
            #pragma unroll
            for (int s=0;s<2;s++) {
                int m = a_m0 + s*16;
                #pragma unroll
                for (int u=0;u<4;u++) As[nxt][(a_k4*4+u)*36 + m] = ((const float*)&va[s])[u];
                int k = b_k0 + s*8;
                *(float4*)&Bs[nxt][k*32 + b_n4*4] = vb[s];
            }
        }
        __syncthreads();
    }

    float* dst = g_opart + (size_t)blockIdx.z * NROW * DRES;
    #pragma unroll
    for (int i=0;i<4;i++) {
        int row = row0 + ty*4 + i;
        float2 u0 = up2(acc2[i][0]), u1 = up2(acc2[i][1]);
        float4 o; o.x = u0.x; o.y = u0.y; o.z = u1.x; o.w = u1.y;
        *(float4*)&dst[(size_t)row*DRES + col0 + tx*4] = o;
    }
}

__global__ void __launch_bounds__(256) out_reduce(
    const float* __restrict__ bout, float* __restrict__ out)
{
    const int STRIDE4 = NROW*DRES/4;
    int i4 = blockIdx.x * 256 + threadIdx.x;
    const float4* p = (const float4*)g_opart;
    float4 a = p[i4], b = p[STRIDE4 + i4], c = p[2*STRIDE4 + i4], d = p[3*STRIDE4 + i4];
    int col = (i4 * 4) % DRES;
    float4 bb = *(const float4*)&bout[col];
    float4 o;
    o.x = a.x + b.x + c.x + d.x + bb.x;
    o.y = a.y + b.y + c.y + d.y + bb.y;
    o.z = a.z + b.z + c.z + d.z + bb.z;
    o.w = a.w + b.w + c.w + d.w + bb.w;
    ((float4*)out)[i4] = o;
}

// ---------------- launch ----------------
extern "C" void kernel_launch(void* const* d_in, const int* in_sizes, int n_in,
                              void* d_out, int out_size)
{
    const float* x     = (const float*)d_in[0];
    const float* e     = (const float*)d_in[1];
    const float* r     = (const float*)d_in[2];
    const float* t     = (const float*)d_in[3];
    const float* Wqs   = (const float*)d_in[4];
    const float* Wks   = (const float*)d_in[5];
    const float* Wvs   = (const float*)d_in[6];
    const float* Wpb   = (const float*)d_in[7];
    const float* Wqp   = (const float*)d_in[8];
    const float* Wkp   = (const float*)d_in[9];
    const float* Wvp   = (const float*)d_in[10];
    const float* gamma = (const float*)d_in[11];
    const float* Wout  = (const float*)d_in[12];
    const float* bout  = (const float*)d_in[13];
    float* out = (float*)d_out;

    proj_gemm<<<dim3(21, 32), 64>>>(x, Wqs, Wks, Wvs, Wqp, Wkp, Wvp);
    point_transform<<<NROW, 96>>>(r, t);

    cudaFuncSetAttribute(ipa_attn, cudaFuncAttributeMaxDynamicSharedMemorySize,
                         SMEM_FLOATS * (int)sizeof(float));
    ipa_attn<<<NROW, 256, SMEM_FLOATS * sizeof(float)>>>(e, r, t, Wpb, gamma);

    out_gemm_sk<<<dim3(12, 32, NSPLIT), 64>>>(Wout);
    out_reduce<<<NROW*DRES/4/256, 256>>>(bout, out);
}

// round 10
// speedup vs baseline: 1.0767x; 1.0767x over previous
#include <cuda_runtime.h>
#include <math.h>

#define NH      8
#define LSEQ    512
#define DRES    384
#define DPAIR   128
#define DS      16
#define TJ      32
#define ROWF    132
#define NROW    1024
#define NFEAT   1280
#define NSPLIT  4
#define KSPLIT  (NFEAT/NSPLIT)

#define SCALE_SCALAR 0.25f
#define SCALE_POINT  0.2357022603955158f   /* 18^-0.5 */
#define SCALE_TOTAL  0.5773502691896258f   /* 3^-0.5  */

typedef unsigned long long ull;

__device__ __forceinline__ ull pk2(float x, float y) {
    ull r; asm("mov.b64 %0,{%1,%2};" : "=l"(r) : "f"(x), "f"(y)); return r;
}
__device__ __forceinline__ ull ffma2(ull a, ull b, ull c) {
    ull d; asm("fma.rn.f32x2 %0,%1,%2,%3;" : "=l"(d) : "l"(a), "l"(b), "l"(c)); return d;
}
__device__ __forceinline__ float2 up2(ull v) {
    float2 r; asm("mov.b64 {%0,%1},%2;" : "=f"(r.x), "=f"(r.y) : "l"(v)); return r;
}
__device__ __forceinline__ void cp_async16(unsigned smem_addr, const void* gptr) {
    asm volatile("cp.async.cg.shared.global [%0], [%1], 16;"
                 :: "r"(smem_addr), "l"(gptr));
}

// ---------------- scratch (device globals; no allocation) ----------------
__device__ float g_qs[2*NH*LSEQ*DS];
__device__ float g_ks[2*NH*LSEQ*DS];
__device__ float g_vs[2*NH*LSEQ*DS];
__device__ float g_qp[2*NH*LSEQ*12];
__device__ float g_kp[2*NH*LSEQ*12];
__device__ float g_vp[2*NH*LSEQ*12];
__device__ float g_praw[NROW*288];
__device__ float g_feat[(size_t)NROW*NFEAT];
__device__ float g_opart[(size_t)NSPLIT*NROW*DRES];

// ---------------- kernel 1: projection GEMM (R8 proven) ------------------
__global__ void __launch_bounds__(64) proj_gemm(
    const float* __restrict__ X,
    const float* __restrict__ Wqs, const float* __restrict__ Wks,
    const float* __restrict__ Wvs, const float* __restrict__ Wqp,
    const float* __restrict__ Wkp, const float* __restrict__ Wvp)
{
    __shared__ float As[2][16*36];
    __shared__ float Bs[2][16*32];
    const int tid = threadIdx.x;
    const int tx = tid & 7, ty = tid >> 3;
    const int row0 = blockIdx.y * 32;
    const int col0 = blockIdx.x * 32;

    const float* Wseg; int segw, cl0;
    if (col0 < 384) {
        int sg = col0 >> 7;
        Wseg = (sg==0) ? Wqs : ((sg==1) ? Wks : Wvs);
        segw = 128; cl0 = col0 & 127;
    } else {
        int c2 = col0 - 384; int sg = c2 / 96;
        Wseg = (sg==0) ? Wqp : ((sg==1) ? Wkp : Wvp);
        segw = 96; cl0 = c2 - sg*96;
    }

    const int a_m0 = tid >> 2, a_k4 = tid & 3;
    const int b_k0 = tid >> 3, b_n4 = tid & 7;

    float acc[4][4];
    #pragma unroll
    for (int i=0;i<4;i++)
        #pragma unroll
        for (int j=0;j<4;j++) acc[i][j]=0.f;

    {
        #pragma unroll
        for (int s=0;s<2;s++) {
            int m = a_m0 + s*16;
            float4 v = *(const float4*)&X[(size_t)(row0+m)*DRES + a_k4*4];
            #pragma unroll
            for (int u=0;u<4;u++) As[0][(a_k4*4+u)*36 + m] = ((const float*)&v)[u];
            int k = b_k0 + s*8;
            *(float4*)&Bs[0][k*32 + b_n4*4] =
                *(const float4*)&Wseg[(size_t)k*segw + cl0 + b_n4*4];
        }
    }
    __syncthreads();

    const int KB = DRES/16;
    for (int kb = 0; kb < KB; kb++) {
        int cur = kb & 1;
        float4 va[2], vb[2];
        bool has = (kb+1 < KB);
        if (has) {
            int k0 = (kb+1)*16;
            #pragma unroll
            for (int s=0;s<2;s++) {
                int m = a_m0 + s*16;
                va[s] = *(const float4*)&X[(size_t)(row0+m)*DRES + k0 + a_k4*4];
                int k = b_k0 + s*8;
                vb[s] = *(const float4*)&Wseg[(size_t)(k0+k)*segw + cl0 + b_n4*4];
            }
        }
        #pragma unroll
        for (int kk = 0; kk < 16; kk++) {
            float4 a = *(const float4*)&As[cur][kk*36 + ty*4];
            float4 b = *(const float4*)&Bs[cur][kk*32 + tx*4];
            const float* ap = (const float*)&a;
            const float* bp = (const float*)&b;
            #pragma unroll
            for (int i=0;i<4;i++)
                #pragma unroll
                for (int j=0;j<4;j++) acc[i][j] += ap[i]*bp[j];
        }
        if (has) {
            int nxt = cur ^ 1;
            #pragma unroll
            for (int s=0;s<2;s++) {
                int m = a_m0 + s*16;
                #pragma unroll
                for (int u=0;u<4;u++) As[nxt][(a_k4*4+u)*36 + m] = ((const float*)&va[s])[u];
                int k = b_k0 + s*8;
                *(float4*)&Bs[nxt][k*32 + b_n4*4] = vb[s];
            }
        }
        __syncthreads();
    }

    #pragma unroll
    for (int i=0;i<4;i++) {
        int row = row0 + ty*4 + i;
        int b = row >> 9, l = row & 511;
        #pragma unroll
        for (int j=0;j<4;j++) {
            int col = col0 + tx*4 + j;
            float v = acc[i][j];
            if (col < 384) {
                int sg = col >> 7;
                int n = (col & 127) >> 4, d = col & 15;
                float* dst = (sg==0) ? g_qs : ((sg==1) ? g_ks : g_vs);
                dst[(((b*NH)+n)*LSEQ + l)*DS + d] = v;
            } else {
                g_praw[row*288 + (col-384)] = v;
            }
        }
    }
}

// ---------------- kernel 2: euclid transform of projected points ---------
__global__ void point_transform(const float* __restrict__ R, const float* __restrict__ T)
{
    int row = blockIdx.x;
    int b = row >> 9, l = row & 511;
    int t = threadIdx.x;
    if (t >= 96) return;
    int tensor = t / 32, idx = t % 32;
    int n = idx >> 2, p = idx & 3;
    const float* xr = &g_praw[row*288 + tensor*96 + n*12 + p*3];
    const float* rr = &R[row*9];
    const float* tt = &T[row*3];
    float x0 = xr[0], x1 = xr[1], x2 = xr[2];
    float* dst = ((tensor==0) ? g_qp : ((tensor==1) ? g_kp : g_vp))
               + (((b*NH)+n)*LSEQ + l)*12 + p*3;
    #pragma unroll
    for (int c = 0; c < 3; c++)
        dst[c] = x0*rr[0*3+c] + x1*rr[1*3+c] + x2*rr[2*3+c] + tt[c];
}

// ------- kernel 3: fused IPA attention, TJ=32 double-buffered cp.async ---
#define EBUF       4224            /* 32*132 floats per e buffer */
#define OFF_E0     0
#define OFF_E1     4224
#define OFF_WPB    8448
#define OFF_LOGIT  9472            /* 8*34 = 272 */
#define OFF_PROB   9744            /* 8*36 = 288 */
#define OFF_PART   10032           /* 256*9 = 2304 */
#define OFF_QS     12336
#define OFF_QP     12464
#define OFF_GAMMA  12560
#define OFF_ALPHA  12568
#define OFF_DENOM  12576
#define OFF_OS     12584
#define OFF_OP     12712
#define SMEM_FLOATS 12808

__global__ void __launch_bounds__(256, 3) ipa_attn(
    const float* __restrict__ E, const float* __restrict__ R,
    const float* __restrict__ T, const float* __restrict__ Wpb,
    const float* __restrict__ gamma)
{
    extern __shared__ float sm[];
    float* Wpb_s   = sm + OFF_WPB;
    float* logit_s = sm + OFF_LOGIT;
    float* prob_s  = sm + OFF_PROB;
    float* part_s  = sm + OFF_PART;
    float* qs_s    = sm + OFF_QS;
    float* qp_s    = sm + OFF_QP;
    float* gamma_s = sm + OFF_GAMMA;
    float* alpha_s = sm + OFF_ALPHA;
    float* denom_s = sm + OFF_DENOM;
    float* os_s    = sm + OFF_OS;
    float* op_s    = sm + OFF_OP;

    int row = blockIdx.x;
    int b = row >> 9, i = row & 511;
    int tid = threadIdx.x;
    int warp = tid >> 5, lane = tid & 31;

    unsigned sbase = (unsigned)__cvta_generic_to_shared(sm);
    const float* Ebi = E + (size_t)row * LSEQ * DPAIR;

    // prologue: tile 0 -> buffer 0 (32 rows x 128 floats, pitch 132)
    {
        const float4* esrc = (const float4*)Ebi;
        #pragma unroll
        for (int it = 0; it < 4; it++) {
            int g = it*256 + tid;
            int j = g >> 5, d = (g & 31) * 4;
            cp_async16(sbase + (unsigned)((OFF_E0 + j*ROWF + d) * 4), esrc + g);
        }
        asm volatile("cp.async.commit_group;");
    }

    for (int k = tid; k < DPAIR*NH; k += 256) Wpb_s[k] = Wpb[k];
    if (tid < 128) { int n = tid >> 4, d = tid & 15;
        qs_s[tid] = g_qs[((b*NH+n)*LSEQ + i)*DS + d]; }
    if (tid < 96)  { int n = tid/12, pc = tid - n*12;
        qp_s[tid] = g_qp[((b*NH+n)*LSEQ + i)*12 + pc]; }
    if (tid < 8) gamma_s[tid] = gamma[tid];

    float m_run = -1e30f, denom = 0.f, acc_sp = 0.f;
    float acc_e[NH][4];
    #pragma unroll
    for (int n=0;n<NH;n++)
        #pragma unroll
        for (int c=0;c<4;c++) acc_e[n][c] = 0.f;

    for (int jt = 0; jt < LSEQ/TJ; jt++) {
        float* e_s = sm + ((jt & 1) ? OFF_E1 : OFF_E0);

        // prefetch next tile into the other buffer
        if (jt + 1 < LSEQ/TJ) {
            const float4* nsrc = (const float4*)(Ebi + (size_t)(jt+1)*TJ*DPAIR);
            unsigned bofs = (jt & 1) ? OFF_E0 : OFF_E1;
            #pragma unroll
            for (int it = 0; it < 4; it++) {
                int g = it*256 + tid;
                int j = g >> 5, d = (g & 31) * 4;
                cp_async16(sbase + (unsigned)((bofs + j*ROWF + d) * 4), nsrc + g);
            }
            asm volatile("cp.async.commit_group;");
            asm volatile("cp.async.wait_group 1;");
        } else {
            asm volatile("cp.async.wait_group 0;");
        }
        __syncthreads();

        int j0 = jt * TJ;

        // --- bias partials: thread (j, oct) covers 16 dims ---
        {
            int j = tid & 31, oct = tid >> 5;
            float pb[NH];
            #pragma unroll
            for (int n=0;n<NH;n++) pb[n] = 0.f;
            const float4* er4 = (const float4*)(e_s + j*ROWF + oct*16);
            const float* wb0 = Wpb_s + oct*16*NH;
            #pragma unroll
            for (int d4 = 0; d4 < 4; d4++) {
                float4 ev = er4[d4];
                const float* wb = wb0 + d4*4*NH;
                #pragma unroll
                for (int n=0;n<NH;n++)
                    pb[n] += ev.x*wb[n] + ev.y*wb[NH+n]
                           + ev.z*wb[2*NH+n] + ev.w*wb[3*NH+n];
            }
            float* po = part_s + (oct*32 + j)*9;
            #pragma unroll
            for (int n=0;n<NH;n++) po[n] = pb[n];
        }
        __syncthreads();

        // --- full logits: thread (j, n), one logit each ---
        {
            int j = tid & 31, n = tid >> 5;
            float bias = 0.f;
            #pragma unroll
            for (int o = 0; o < 8; o++) bias += part_s[(o*32+j)*9 + n];
            const float4* kr = (const float4*)(g_ks + ((b*NH+n)*LSEQ + j0 + j)*DS);
            float dot = 0.f;
            #pragma unroll
            for (int q4 = 0; q4 < 4; q4++) {
                float4 kv = kr[q4];
                const float* qq = qs_s + n*DS + q4*4;
                dot += qq[0]*kv.x + qq[1]*kv.y + qq[2]*kv.z + qq[3]*kv.w;
            }
            const float4* kp = (const float4*)(g_kp + ((b*NH+n)*LSEQ + j0 + j)*12);
            float sq = 0.f;
            #pragma unroll
            for (int q4 = 0; q4 < 3; q4++) {
                float4 kv = kp[q4];
                const float* qq = qp_s + n*12 + q4*4;
                float d0 = qq[0]-kv.x, d1 = qq[1]-kv.y, d2 = qq[2]-kv.z, d3 = qq[3]-kv.w;
                sq += d0*d0 + d1*d1 + d2*d2 + d3*d3;
            }
            logit_s[n*34 + j] = SCALE_TOTAL*(SCALE_SCALAR*dot + bias
                                - 0.5f*SCALE_POINT*gamma_s[n]*sq);
        }
        __syncthreads();

        // --- per-head online softmax + out_s / out_p (warp = head) ---
        {
            int n = warp;
            float l = logit_s[n*34 + lane];
            float mt = l;
            #pragma unroll
            for (int o = 16; o > 0; o >>= 1)
                mt = fmaxf(mt, __shfl_xor_sync(0xffffffffu, mt, o));
            float m_new = fmaxf(m_run, mt);
            float alpha = __expf(m_run - m_new);
            float p = __expf(l - m_new);
            prob_s[n*36 + lane] = p;
            float s = p;
            #pragma unroll
            for (int o = 16; o > 0; o >>= 1)
                s += __shfl_xor_sync(0xffffffffu, s, o);
            denom = denom*alpha + s;
            m_run = m_new;
            if (lane == 0) alpha_s[n] = alpha;
            __syncwarp();
            acc_sp *= alpha;
            if (lane < 28) {
                const float* vb; int st;
                if (lane < 16) { vb = g_vs + ((b*NH+n)*LSEQ + j0)*DS + lane; st = DS; }
                else           { vb = g_vp + ((b*NH+n)*LSEQ + j0)*12 + (lane-16); st = 12; }
                float a = 0.f;
                #pragma unroll 8
                for (int j = 0; j < TJ; j++) a += prob_s[n*36+j] * vb[j*st];
                acc_sp += a;
            }
        }
        __syncthreads();

        // --- out_pair accumulate: warp owns 4 j rows, lane owns 4 dims ---
        {
            #pragma unroll
            for (int n=0;n<NH;n++) {
                float a = alpha_s[n];
                #pragma unroll
                for (int c=0;c<4;c++) acc_e[n][c] *= a;
            }
            int jb = warp*4;
            #pragma unroll
            for (int jj = 0; jj < 4; jj++) {
                int j = jb + jj;
                float4 ev = *(const float4*)(e_s + j*ROWF + lane*4);
                #pragma unroll
                for (int n=0;n<NH;n++) {
                    float p = prob_s[n*36 + j];
                    acc_e[n][0] += p*ev.x; acc_e[n][1] += p*ev.y;
                    acc_e[n][2] += p*ev.z; acc_e[n][3] += p*ev.w;
                }
            }
        }
        __syncthreads();
    }

    // ------------- finalize -------------
    float inv_d = 1.f / denom;
    if (lane == 0) denom_s[warp] = denom;
    if (lane < 16)      os_s[warp*16 + lane]        = acc_sp * inv_d;
    else if (lane < 28) op_s[warp*12 + (lane-16)]   = acc_sp * inv_d;
    __syncthreads();

    // cross-warp reduce of out_pair partials via both e buffers (8448 floats)
    float* red = sm + OFF_E0;
    #pragma unroll
    for (int n=0;n<NH;n++)
        *(float4*)(red + (warp*NH + n)*128 + lane*4) =
            make_float4(acc_e[n][0], acc_e[n][1], acc_e[n][2], acc_e[n][3]);
    __syncthreads();

    float* feat = g_feat + (size_t)row * NFEAT;
    #pragma unroll
    for (int k = 0; k < 4; k++) {
        int o = tid + k*256;
        int n = o >> 7, d = o & 127;
        float s = 0.f;
        #pragma unroll
        for (int w = 0; w < 8; w++) s += red[(w*NH+n)*128 + d];
        feat[128 + n*128 + d] = s / denom_s[n];
    }
    if (tid < 128) feat[tid] = os_s[tid];
    if (tid < 32) {
        int n = tid >> 2, p = tid & 3;
        const float* rr = R + row*9;
        const float* tt = T + row*3;
        float o0 = op_s[n*12+p*3+0] - tt[0];
        float o1 = op_s[n*12+p*3+1] - tt[1];
        float o2 = op_s[n*12+p*3+2] - tt[2];
        float nsq = 0.f;
        #pragma unroll
        for (int c = 0; c < 3; c++) {
            float lc = o0*rr[c*3+0] + o1*rr[c*3+1] + o2*rr[c*3+2];
            feat[1152 + n*12 + p*3 + c] = lc;
            nsq += lc*lc;
        }
        feat[1248 + n*4 + p] = sqrtf(nsq);
    }
}

// ------------- kernel 4: output GEMM, 4-way split-K partials --------------
__global__ void __launch_bounds__(64) out_gemm_sk(const float* __restrict__ Wout)
{
    __shared__ float As[2][16*36];
    __shared__ float Bs[2][16*32];
    const int tid = threadIdx.x;
    const int tx = tid & 7, ty = tid >> 3;
    const int row0 = blockIdx.y * 32;
    const int col0 = blockIdx.x * 32;
    const int kbase = blockIdx.z * KSPLIT;

    const int a_m0 = tid >> 2, a_k4 = tid & 3;
    const int b_k0 = tid >> 3, b_n4 = tid & 7;

    ull acc2[4][2];
    #pragma unroll
    for (int i=0;i<4;i++) { acc2[i][0]=0ull; acc2[i][1]=0ull; }

    {
        #pragma unroll
        for (int s=0;s<2;s++) {
            int m = a_m0 + s*16;
            float4 v = *(const float4*)&g_feat[(size_t)(row0+m)*NFEAT + kbase + a_k4*4];
            #pragma unroll
            for (int u=0;u<4;u++) As[0][(a_k4*4+u)*36 + m] = ((const float*)&v)[u];
            int k = b_k0 + s*8;
            *(float4*)&Bs[0][k*32 + b_n4*4] =
                *(const float4*)&Wout[(size_t)(kbase+k)*DRES + col0 + b_n4*4];
        }
    }
    __syncthreads();

    const int KB = KSPLIT/16;
    for (int kb = 0; kb < KB; kb++) {
        int cur = kb & 1;
        float4 va[2], vb[2];
        bool has = (kb+1 < KB);
        if (has) {
            int k0 = kbase + (kb+1)*16;
            #pragma unroll
            for (int s=0;s<2;s++) {
                int m = a_m0 + s*16;
                va[s] = *(const float4*)&g_feat[(size_t)(row0+m)*NFEAT + k0 + a_k4*4];
                int k = b_k0 + s*8;
                vb[s] = *(const float4*)&Wout[(size_t)(k0+k)*DRES + col0 + b_n4*4];
            }
        }
        #pragma unroll
        for (int kk = 0; kk < 16; kk++) {
            float4 a = *(const float4*)&As[cur][kk*36 + ty*4];
            float4 b = *(const float4*)&Bs[cur][kk*32 + tx*4];
            ull b01 = pk2(b.x, b.y), b23 = pk2(b.z, b.w);
            const float* ap = (const float*)&a;
            #pragma unroll
            for (int i=0;i<4;i++) {
                ull aa = pk2(ap[i], ap[i]);
                acc2[i][0] = ffma2(aa, b01, acc2[i][0]);
                acc2[i][1] = ffma2(aa, b23, acc2[i][1]);
            }
        }
        if (has) {
            int nxt = cur ^ 1;
            #pragma unroll
            for (int s=0;s<2;s++) {
                int m = a_m0 + s*16;
                #pragma unroll
                for (int u=0;u<4;u++) As[nxt][(a_k4*4+u)*36 + m] = ((const float*)&va[s])[u];
                int k = b_k0 + s*8;
                *(float4*)&Bs[nxt][k*32 + b_n4*4] = vb[s];
            }
        }
        __syncthreads();
    }

    float* dst = g_opart + (size_t)blockIdx.z * NROW * DRES;
    #pragma unroll
    for (int i=0;i<4;i++) {
        int row = row0 + ty*4 + i;
        float2 u0 = up2(acc2[i][0]), u1 = up2(acc2[i][1]);
        float4 o; o.x = u0.x; o.y = u0.y; o.z = u1.x; o.w = u1.y;
        *(float4*)&dst[(size_t)row*DRES + col0 + tx*4] = o;
    }
}

__global__ void __launch_bounds__(256) out_reduce(
    const float* __restrict__ bout, float* __restrict__ out)
{
    const int STRIDE4 = NROW*DRES/4;
    int i4 = blockIdx.x * 256 + threadIdx.x;
    const float4* p = (const float4*)g_opart;
    float4 a = p[i4], b = p[STRIDE4 + i4], c = p[2*STRIDE4 + i4], d = p[3*STRIDE4 + i4];
    int col = (i4 * 4) % DRES;
    float4 bb = *(const float4*)&bout[col];
    float4 o;
    o.x = a.x + b.x + c.x + d.x + bb.x;
    o.y = a.y + b.y + c.y + d.y + bb.y;
    o.z = a.z + b.z + c.z + d.z + bb.z;
    o.w = a.w + b.w + c.w + d.w + bb.w;
    ((float4*)out)[i4] = o;
}

// ---------------- launch ----------------
extern "C" void kernel_launch(void* const* d_in, const int* in_sizes, int n_in,
                              void* d_out, int out_size)
{
    const float* x     = (const float*)d_in[0];
    const float* e     = (const float*)d_in[1];
    const float* r     = (const float*)d_in[2];
    const float* t     = (const float*)d_in[3];
    const float* Wqs   = (const float*)d_in[4];
    const float* Wks   = (const float*)d_in[5];
    const float* Wvs   = (const float*)d_in[6];
    const float* Wpb   = (const float*)d_in[7];
    const float* Wqp   = (const float*)d_in[8];
    const float* Wkp   = (const float*)d_in[9];
    const float* Wvp   = (const float*)d_in[10];
    const float* gamma = (const float*)d_in[11];
    const float* Wout  = (const float*)d_in[12];
    const float* bout  = (const float*)d_in[13];
    float* out = (float*)d_out;

    proj_gemm<<<dim3(21, 32), 64>>>(x, Wqs, Wks, Wvs, Wqp, Wkp, Wvp);
    point_transform<<<NROW, 96>>>(r, t);

    cudaFuncSetAttribute(ipa_attn, cudaFuncAttributeMaxDynamicSharedMemorySize,
                         SMEM_FLOATS * (int)sizeof(float));
    ipa_attn<<<NROW, 256, SMEM_FLOATS * sizeof(float)>>>(e, r, t, Wpb, gamma);

    out_gemm_sk<<<dim3(12, 32, NSPLIT), 64>>>(Wout);
    out_reduce<<<NROW*DRES/4/256, 256>>>(bout, out);
}

// round 11
// speedup vs baseline: 1.1575x; 1.0750x over previous
#include <cuda_runtime.h>
#include <math.h>

#define NH      8
#define LSEQ    512
#define DRES    384
#define DPAIR   128
#define DS      16
#define TJ      64
#define ROWF    132
#define NROW    1024
#define NFEAT   1280
#define NSPLIT  4
#define KSPLIT  (NFEAT/NSPLIT)

#define SCALE_SCALAR 0.25f
#define SCALE_POINT  0.2357022603955158f   /* 18^-0.5 */
#define SCALE_TOTAL  0.5773502691896258f   /* 3^-0.5  */

typedef unsigned long long ull;

__device__ __forceinline__ ull pk2(float x, float y) {
    ull r; asm("mov.b64 %0,{%1,%2};" : "=l"(r) : "f"(x), "f"(y)); return r;
}
__device__ __forceinline__ ull ffma2(ull a, ull b, ull c) {
    ull d; asm("fma.rn.f32x2 %0,%1,%2,%3;" : "=l"(d) : "l"(a), "l"(b), "l"(c)); return d;
}
__device__ __forceinline__ float2 up2(ull v) {
    float2 r; asm("mov.b64 {%0,%1},%2;" : "=f"(r.x), "=f"(r.y) : "l"(v)); return r;
}
__device__ __forceinline__ void cp_async16(unsigned smem_addr, const void* gptr) {
    asm volatile("cp.async.cg.shared.global [%0], [%1], 16;"
                 :: "r"(smem_addr), "l"(gptr));
}

// ---------------- scratch (device globals; no allocation) ----------------
__device__ float g_qs[2*NH*LSEQ*DS];
__device__ float g_ks[2*NH*LSEQ*DS];
__device__ float g_vs[2*NH*LSEQ*DS];
__device__ float g_qp[2*NH*LSEQ*12];
__device__ float g_kp[2*NH*LSEQ*12];
__device__ float g_vp[2*NH*LSEQ*12];
__device__ float g_praw[NROW*288];
__device__ float g_feat[(size_t)NROW*NFEAT];
__device__ float g_opart[(size_t)NSPLIT*NROW*DRES];

// ---------------- kernel 1: projection GEMM ------------------------------
__global__ void __launch_bounds__(64) proj_gemm(
    const float* __restrict__ X,
    const float* __restrict__ Wqs, const float* __restrict__ Wks,
    const float* __restrict__ Wvs, const float* __restrict__ Wqp,
    const float* __restrict__ Wkp, const float* __restrict__ Wvp)
{
    __shared__ float As[2][16*36];
    __shared__ float Bs[2][16*32];
    const int tid = threadIdx.x;
    const int tx = tid & 7, ty = tid >> 3;
    const int row0 = blockIdx.y * 32;
    const int col0 = blockIdx.x * 32;

    const float* Wseg; int segw, cl0;
    if (col0 < 384) {
        int sg = col0 >> 7;
        Wseg = (sg==0) ? Wqs : ((sg==1) ? Wks : Wvs);
        segw = 128; cl0 = col0 & 127;
    } else {
        int c2 = col0 - 384; int sg = c2 / 96;
        Wseg = (sg==0) ? Wqp : ((sg==1) ? Wkp : Wvp);
        segw = 96; cl0 = c2 - sg*96;
    }

    const int a_m0 = tid >> 2, a_k4 = tid & 3;
    const int b_k0 = tid >> 3, b_n4 = tid & 7;

    float acc[4][4];
    #pragma unroll
    for (int i=0;i<4;i++)
        #pragma unroll
        for (int j=0;j<4;j++) acc[i][j]=0.f;

    {
        #pragma unroll
        for (int s=0;s<2;s++) {
            int m = a_m0 + s*16;
            float4 v = *(const float4*)&X[(size_t)(row0+m)*DRES + a_k4*4];
            #pragma unroll
            for (int u=0;u<4;u++) As[0][(a_k4*4+u)*36 + m] = ((const float*)&v)[u];
            int k = b_k0 + s*8;
            *(float4*)&Bs[0][k*32 + b_n4*4] =
                *(const float4*)&Wseg[(size_t)k*segw + cl0 + b_n4*4];
        }
    }
    __syncthreads();

    const int KB = DRES/16;
    for (int kb = 0; kb < KB; kb++) {
        int cur = kb & 1;
        float4 va[2], vb[2];
        bool has = (kb+1 < KB);
        if (has) {
            int k0 = (kb+1)*16;
            #pragma unroll
            for (int s=0;s<2;s++) {
                int m = a_m0 + s*16;
                va[s] = *(const float4*)&X[(size_t)(row0+m)*DRES + k0 + a_k4*4];
                int k = b_k0 + s*8;
                vb[s] = *(const float4*)&Wseg[(size_t)(k0+k)*segw + cl0 + b_n4*4];
            }
        }
        #pragma unroll
        for (int kk = 0; kk < 16; kk++) {
            float4 a = *(const float4*)&As[cur][kk*36 + ty*4];
            float4 b = *(const float4*)&Bs[cur][kk*32 + tx*4];
            const float* ap = (const float*)&a;
            const float* bp = (const float*)&b;
            #pragma unroll
            for (int i=0;i<4;i++)
                #pragma unroll
                for (int j=0;j<4;j++) acc[i][j] += ap[i]*bp[j];
        }
        if (has) {
            int nxt = cur ^ 1;
            #pragma unroll
            for (int s=0;s<2;s++) {
                int m = a_m0 + s*16;
                #pragma unroll
                for (int u=0;u<4;u++) As[nxt][(a_k4*4+u)*36 + m] = ((const float*)&va[s])[u];
                int k = b_k0 + s*8;
                *(float4*)&Bs[nxt][k*32 + b_n4*4] = vb[s];
            }
        }
        __syncthreads();
    }

    #pragma unroll
    for (int i=0;i<4;i++) {
        int row = row0 + ty*4 + i;
        int b = row >> 9, l = row & 511;
        #pragma unroll
        for (int j=0;j<4;j++) {
            int col = col0 + tx*4 + j;
            float v = acc[i][j];
            if (col < 384) {
                int sg = col >> 7;
                int n = (col & 127) >> 4, d = col & 15;
                float* dst = (sg==0) ? g_qs : ((sg==1) ? g_ks : g_vs);
                dst[(((b*NH)+n)*LSEQ + l)*DS + d] = v;
            } else {
                g_praw[row*288 + (col-384)] = v;
            }
        }
    }
}

// ---------------- kernel 2: euclid transform of projected points ---------
__global__ void point_transform(const float* __restrict__ R, const float* __restrict__ T)
{
    int row = blockIdx.x;
    int b = row >> 9, l = row & 511;
    int t = threadIdx.x;
    if (t >= 96) return;
    int tensor = t / 32, idx = t % 32;
    int n = idx >> 2, p = idx & 3;
    const float* xr = &g_praw[row*288 + tensor*96 + n*12 + p*3];
    const float* rr = &R[row*9];
    const float* tt = &T[row*3];
    float x0 = xr[0], x1 = xr[1], x2 = xr[2];
    float* dst = ((tensor==0) ? g_qp : ((tensor==1) ? g_kp : g_vp))
               + (((b*NH)+n)*LSEQ + l)*12 + p*3;
    #pragma unroll
    for (int c = 0; c < 3; c++)
        dst[c] = x0*rr[0*3+c] + x1*rr[1*3+c] + x2*rr[2*3+c] + tt[c];
}

// ---------------- kernel 3: fused IPA attention, cp.async double-buffer --
#define EBUF       8448            /* 64*132 floats per e buffer */
#define OFF_E0     0
#define OFF_E1     8448
#define OFF_WPB    16896
#define OFF_LOGIT  17920
#define OFF_PROB   18448
#define OFF_PART   18976
#define OFF_QS     21280
#define OFF_QP     21408
#define OFF_GAMMA  21504
#define OFF_ALPHA  21512
#define OFF_DENOM  21520
#define OFF_OS     21528
#define OFF_OP     21656
#define SMEM_FLOATS 21760

__global__ void __launch_bounds__(256) ipa_attn(
    const float* __restrict__ E, const float* __restrict__ R,
    const float* __restrict__ T, const float* __restrict__ Wpb,
    const float* __restrict__ gamma)
{
    extern __shared__ float sm[];
    float* Wpb_s   = sm + OFF_WPB;
    float* logit_s = sm + OFF_LOGIT;
    float* prob_s  = sm + OFF_PROB;
    float* part_s  = sm + OFF_PART;
    float* qs_s    = sm + OFF_QS;
    float* qp_s    = sm + OFF_QP;
    float* gamma_s = sm + OFF_GAMMA;
    float* alpha_s = sm + OFF_ALPHA;
    float* denom_s = sm + OFF_DENOM;
    float* os_s    = sm + OFF_OS;
    float* op_s    = sm + OFF_OP;

    int row = blockIdx.x;
    int b = row >> 9, i = row & 511;
    int tid = threadIdx.x;
    int warp = tid >> 5, lane = tid & 31;

    unsigned sbase = (unsigned)__cvta_generic_to_shared(sm);
    const float* Ebi = E + (size_t)row * LSEQ * DPAIR;

    // prologue: tile 0 -> buffer 0
    {
        const float4* esrc = (const float4*)Ebi;
        #pragma unroll
        for (int it = 0; it < 8; it++) {
            int g = it*256 + tid;
            int j = g >> 5, d = (g & 31) * 4;
            cp_async16(sbase + (unsigned)((OFF_E0 + j*ROWF + d) * 4), esrc + g);
        }
        asm volatile("cp.async.commit_group;");
    }

    for (int k = tid; k < DPAIR*NH; k += 256) Wpb_s[k] = Wpb[k];
    if (tid < 128) { int n = tid >> 4, d = tid & 15;
        qs_s[tid] = g_qs[((b*NH+n)*LSEQ + i)*DS + d]; }
    if (tid < 96)  { int n = tid/12, pc = tid - n*12;
        qp_s[tid] = g_qp[((b*NH+n)*LSEQ + i)*12 + pc]; }
    if (tid < 8) gamma_s[tid] = gamma[tid];

    float m_run = -1e30f, denom = 0.f, acc_sp = 0.f;
    float acc_e[NH][4];
    #pragma unroll
    for (int n=0;n<NH;n++)
        #pragma unroll
        for (int c=0;c<4;c++) acc_e[n][c] = 0.f;

    for (int jt = 0; jt < LSEQ/TJ; jt++) {
        float* e_s = sm + ((jt & 1) ? OFF_E1 : OFF_E0);

        // issue prefetch of next tile into the other buffer
        if (jt + 1 < LSEQ/TJ) {
            const float4* nsrc = (const float4*)(Ebi + (size_t)(jt+1)*TJ*DPAIR);
            unsigned bofs = (jt & 1) ? OFF_E0 : OFF_E1;
            #pragma unroll
            for (int it = 0; it < 8; it++) {
                int g = it*256 + tid;
                int j = g >> 5, d = (g & 31) * 4;
                cp_async16(sbase + (unsigned)((bofs + j*ROWF + d) * 4), nsrc + g);
            }
            asm volatile("cp.async.commit_group;");
            asm volatile("cp.async.wait_group 1;");
        } else {
            asm volatile("cp.async.wait_group 0;");
        }
        __syncthreads();

        int j0 = jt * TJ;

        // --- bias partials: thread (j, quad); Wpb is [d][n] row-major so a
        //     float4 pair fetches all 8 head-weights of one dim (was 256
        //     scalar LDS per thread-tile, now 64 LDS.128) ---
        {
            int j = tid & 63, quad = tid >> 6;
            float pb[NH];
            #pragma unroll
            for (int n=0;n<NH;n++) pb[n] = 0.f;
            const float4* er4 = (const float4*)(e_s + j*ROWF + quad*32);
            #pragma unroll
            for (int d4 = 0; d4 < 8; d4++) {
                float4 ev = er4[d4];
                const float* evp = (const float*)&ev;
                #pragma unroll
                for (int r = 0; r < 4; r++) {
                    const float* wrow = Wpb_s + (quad*32 + d4*4 + r)*NH;
                    float4 wA = *(const float4*)(wrow);
                    float4 wB = *(const float4*)(wrow + 4);
                    float e1 = evp[r];
                    pb[0] += e1*wA.x; pb[1] += e1*wA.y;
                    pb[2] += e1*wA.z; pb[3] += e1*wA.w;
                    pb[4] += e1*wB.x; pb[5] += e1*wB.y;
                    pb[6] += e1*wB.z; pb[7] += e1*wB.w;
                }
            }
            float* po = part_s + (quad*64 + j)*9;
            #pragma unroll
            for (int n=0;n<NH;n++) po[n] = pb[n];
        }
        __syncthreads();

        // --- full logits (2 heads per thread) ---
        {
            int j = tid & 63, nb = tid >> 6;
            #pragma unroll
            for (int h = 0; h < 2; h++) {
                int n = nb + h*4;
                float bias = part_s[(0*64+j)*9+n] + part_s[(1*64+j)*9+n]
                           + part_s[(2*64+j)*9+n] + part_s[(3*64+j)*9+n];
                const float4* kr = (const float4*)(g_ks + ((b*NH+n)*LSEQ + j0 + j)*DS);
                float dot = 0.f;
                #pragma unroll
                for (int q4 = 0; q4 < 4; q4++) {
                    float4 kv = kr[q4];
                    const float* qq = qs_s + n*DS + q4*4;
                    dot += qq[0]*kv.x + qq[1]*kv.y + qq[2]*kv.z + qq[3]*kv.w;
                }
                const float4* kp = (const float4*)(g_kp + ((b*NH+n)*LSEQ + j0 + j)*12);
                float sq = 0.f;
                #pragma unroll
                for (int q4 = 0; q4 < 3; q4++) {
                    float4 kv = kp[q4];
                    const float* qq = qp_s + n*12 + q4*4;
                    float d0 = qq[0]-kv.x, d1 = qq[1]-kv.y, d2 = qq[2]-kv.z, d3 = qq[3]-kv.w;
                    sq += d0*d0 + d1*d1 + d2*d2 + d3*d3;
                }
                logit_s[n*66 + j] = SCALE_TOTAL*(SCALE_SCALAR*dot + bias
                                    - 0.5f*SCALE_POINT*gamma_s[n]*sq);
            }
        }
        __syncthreads();

        // --- per-head online softmax + out_s / out_p (warp = head) ---
        {
            int n = warp;
            float l0 = logit_s[n*66 + lane], l1 = logit_s[n*66 + lane + 32];
            float mt = fmaxf(l0, l1);
            #pragma unroll
            for (int o = 16; o > 0; o >>= 1)
                mt = fmaxf(mt, __shfl_xor_sync(0xffffffffu, mt, o));
            float m_new = fmaxf(m_run, mt);
            float alpha = __expf(m_run - m_new);
            float p0 = __expf(l0 - m_new), p1 = __expf(l1 - m_new);
            prob_s[n*66 + lane] = p0;
            prob_s[n*66 + lane + 32] = p1;
            float s = p0 + p1;
            #pragma unroll
            for (int o = 16; o > 0; o >>= 1)
                s += __shfl_xor_sync(0xffffffffu, s, o);
            denom = denom*alpha + s;
            m_run = m_new;
            if (lane == 0) alpha_s[n] = alpha;
            __syncwarp();
            acc_sp *= alpha;
            if (lane < 28) {
                const float* vb; int st;
                if (lane < 16) { vb = g_vs + ((b*NH+n)*LSEQ + j0)*DS + lane; st = DS; }
                else           { vb = g_vp + ((b*NH+n)*LSEQ + j0)*12 + (lane-16); st = 12; }
                float a = 0.f;
                #pragma unroll 8
                for (int j = 0; j < TJ; j++) a += prob_s[n*66+j] * vb[j*st];
                acc_sp += a;
            }
        }
        __syncthreads();   // alphas + probs visible to all warps

        // --- out_pair partial accumulate: warp owns a j-slice, lane owns 4 dims
        {
            #pragma unroll
            for (int n=0;n<NH;n++) {
                float a = alpha_s[n];
                #pragma unroll
                for (int c=0;c<4;c++) acc_e[n][c] *= a;
            }
            int jb = warp*8;
            #pragma unroll
            for (int jj = 0; jj < 8; jj++) {
                int j = jb + jj;
                float4 ev = *(const float4*)(e_s + j*ROWF + lane*4);
                #pragma unroll
                for (int n=0;n<NH;n++) {
                    float p = prob_s[n*66 + j];
                    acc_e[n][0] += p*ev.x; acc_e[n][1] += p*ev.y;
                    acc_e[n][2] += p*ev.z; acc_e[n][3] += p*ev.w;
                }
            }
        }
        __syncthreads();   // all reads done before buffer reuse next iter
    }

    // ------------- finalize -------------
    float inv_d = 1.f / denom;
    if (lane == 0) denom_s[warp] = denom;
    if (lane < 16)      os_s[warp*16 + lane]        = acc_sp * inv_d;
    else if (lane < 28) op_s[warp*12 + (lane-16)]   = acc_sp * inv_d;
    __syncthreads();

    // cross-warp reduce of out_pair partials via e buffer 0 (reused)
    float* red = sm + OFF_E0;
    #pragma unroll
    for (int n=0;n<NH;n++)
        *(float4*)(red + (warp*NH + n)*128 + lane*4) =
            make_float4(acc_e[n][0], acc_e[n][1], acc_e[n][2], acc_e[n][3]);
    __syncthreads();

    float* feat = g_feat + (size_t)row * NFEAT;
    #pragma unroll
    for (int k = 0; k < 4; k++) {
        int o = tid + k*256;
        int n = o >> 7, d = o & 127;
        float s = 0.f;
        #pragma unroll
        for (int w = 0; w < 8; w++) s += red[(w*NH+n)*128 + d];
        feat[128 + n*128 + d] = s / denom_s[n];
    }
    if (tid < 128) feat[tid] = os_s[tid];
    if (tid < 32) {
        int n = tid >> 2, p = tid & 3;
        const float* rr = R + row*9;
        const float* tt = T + row*3;
        float o0 = op_s[n*12+p*3+0] - tt[0];
        float o1 = op_s[n*12+p*3+1] - tt[1];
        float o2 = op_s[n*12+p*3+2] - tt[2];
        float nsq = 0.f;
        #pragma unroll
        for (int c = 0; c < 3; c++) {
            float lc = o0*rr[c*3+0] + o1*rr[c*3+1] + o2*rr[c*3+2];
            feat[1152 + n*12 + p*3 + c] = lc;
            nsq += lc*lc;
        }
        feat[1248 + n*4 + p] = sqrtf(nsq);
    }
}

// ------------- kernel 4: output GEMM, 4-way split-K partials --------------
__global__ void __launch_bounds__(64) out_gemm_sk(const float* __restrict__ Wout)
{
    __shared__ float As[2][16*36];
    __shared__ float Bs[2][16*32];
    const int tid = threadIdx.x;
    const int tx = tid & 7, ty = tid >> 3;
    const int row0 = blockIdx.y * 32;
    const int col0 = blockIdx.x * 32;
    const int kbase = blockIdx.z * KSPLIT;

    const int a_m0 = tid >> 2, a_k4 = tid & 3;
    const int b_k0 = tid >> 3, b_n4 = tid & 7;

    ull acc2[4][2];
    #pragma unroll
    for (int i=0;i<4;i++) { acc2[i][0]=0ull; acc2[i][1]=0ull; }

    {
        #pragma unroll
        for (int s=0;s<2;s++) {
            int m = a_m0 + s*16;
            float4 v = *(const float4*)&g_feat[(size_t)(row0+m)*NFEAT + kbase + a_k4*4];
            #pragma unroll
            for (int u=0;u<4;u++) As[0][(a_k4*4+u)*36 + m] = ((const float*)&v)[u];
            int k = b_k0 + s*8;
            *(float4*)&Bs[0][k*32 + b_n4*4] =
                *(const float4*)&Wout[(size_t)(kbase+k)*DRES + col0 + b_n4*4];
        }
    }
    __syncthreads();

    const int KB = KSPLIT/16;
    for (int kb = 0; kb < KB; kb++) {
        int cur = kb & 1;
        float4 va[2], vb[2];
        bool has = (kb+1 < KB);
        if (has) {
            int k0 = kbase + (kb+1)*16;
            #pragma unroll
            for (int s=0;s<2;s++) {
                int m = a_m0 + s*16;
                va[s] = *(const float4*)&g_feat[(size_t)(row0+m)*NFEAT + k0 + a_k4*4];
                int k = b_k0 + s*8;
                vb[s] = *(const float4*)&Wout[(size_t)(k0+k)*DRES + col0 + b_n4*4];
            }
        }
        #pragma unroll
        for (int kk = 0; kk < 16; kk++) {
            float4 a = *(const float4*)&As[cur][kk*36 + ty*4];
            float4 b = *(const float4*)&Bs[cur][kk*32 + tx*4];
            ull b01 = pk2(b.x, b.y), b23 = pk2(b.z, b.w);
            const float* ap = (const float*)&a;
            #pragma unroll
            for (int i=0;i<4;i++) {
                ull aa = pk2(ap[i], ap[i]);
                acc2[i][0] = ffma2(aa, b01, acc2[i][0]);
                acc2[i][1] = ffma2(aa, b23, acc2[i][1]);
            }
        }
        if (has) {
            int nxt = cur ^ 1;
            #pragma unroll
            for (int s=0;s<2;s++) {
                int m = a_m0 + s*16;
                #pragma unroll
                for (int u=0;u<4;u++) As[nxt][(a_k4*4+u)*36 + m] = ((const float*)&va[s])[u];
                int k = b_k0 + s*8;
                *(float4*)&Bs[nxt][k*32 + b_n4*4] = vb[s];
            }
        }
        __syncthreads();
    }

    float* dst = g_opart + (size_t)blockIdx.z * NROW * DRES;
    #pragma unroll
    for (int i=0;i<4;i++) {
        int row = row0 + ty*4 + i;
        float2 u0 = up2(acc2[i][0]), u1 = up2(acc2[i][1]);
        float4 o; o.x = u0.x; o.y = u0.y; o.z = u1.x; o.w = u1.y;
        *(float4*)&dst[(size_t)row*DRES + col0 + tx*4] = o;
    }
}

__global__ void __launch_bounds__(256) out_reduce(
    const float* __restrict__ bout, float* __restrict__ out)
{
    const int STRIDE4 = NROW*DRES/4;
    int i4 = blockIdx.x * 256 + threadIdx.x;
    const float4* p = (const float4*)g_opart;
    float4 a = p[i4], b = p[STRIDE4 + i4], c = p[2*STRIDE4 + i4], d = p[3*STRIDE4 + i4];
    int col = (i4 * 4) % DRES;
    float4 bb = *(const float4*)&bout[col];
    float4 o;
    o.x = a.x + b.x + c.x + d.x + bb.x;
    o.y = a.y + b.y + c.y + d.y + bb.y;
    o.z = a.z + b.z + c.z + d.z + bb.z;
    o.w = a.w + b.w + c.w + d.w + bb.w;
    ((float4*)out)[i4] = o;
}

// ---------------- launch ----------------
extern "C" void kernel_launch(void* const* d_in, const int* in_sizes, int n_in,
                              void* d_out, int out_size)
{
    const float* x     = (const float*)d_in[0];
    const float* e     = (const float*)d_in[1];
    const float* r     = (const float*)d_in[2];
    const float* t     = (const float*)d_in[3];
    const float* Wqs   = (const float*)d_in[4];
    const float* Wks   = (const float*)d_in[5];
    const float* Wvs   = (const float*)d_in[6];
    const float* Wpb   = (const float*)d_in[7];
    const float* Wqp   = (const float*)d_in[8];
    const float* Wkp   = (const float*)d_in[9];
    const float* Wvp   = (const float*)d_in[10];
    const float* gamma = (const float*)d_in[11];
    const float* Wout  = (const float*)d_in[12];
    const float* bout  = (const float*)d_in[13];
    float* out = (float*)d_out;

    proj_gemm<<<dim3(21, 32), 64>>>(x, Wqs, Wks, Wvs, Wqp, Wkp, Wvp);
    point_transform<<<NROW, 96>>>(r, t);

    cudaFuncSetAttribute(ipa_attn, cudaFuncAttributeMaxDynamicSharedMemorySize,
                         SMEM_FLOATS * (int)sizeof(float));
    ipa_attn<<<NROW, 256, SMEM_FLOATS * sizeof(float)>>>(e, r, t, Wpb, gamma);

    out_gemm_sk<<<dim3(12, 32, NSPLIT), 64>>>(Wout);
    out_reduce<<<NROW*DRES/4/256, 256>>>(bout, out);
}